// round 14
// baseline (speedup 1.0000x reference)
#include <cuda_runtime.h>
#include <math.h>

#define BATCH     262144
#define MARGIN    1.0f
#define EPS_V     1e-6f

__device__ __forceinline__ float dot4(float4 a, float4 b) {
    return fmaf(a.x, b.x, fmaf(a.y, b.y, fmaf(a.z, b.z, a.w * b.w)));
}

// One warp per triple; even warp = pos, odd warp = neg of the same element.
// 256 threads (8 warps, 4 elements) x 8 blocks/SM = 64 warps/SM resident.
// Single fused butterfly for (headp.head - tailp.tail): reduction is linear,
// so reduce the per-lane difference once instead of two separate dots.
__global__ __launch_bounds__(256, 8)
void transd_kernel(const float* __restrict__ ent,
                   const float* __restrict__ entp,
                   const float* __restrict__ rel,
                   const float* __restrict__ relp,
                   const int*   __restrict__ pos,
                   const int*   __restrict__ neg,
                   float*       __restrict__ out)
{
    const int lane = threadIdx.x & 31;
    const int warp = threadIdx.x >> 5;          // 0..7
    const int pair = warp >> 1;                 // 0..3
    const int elem = blockIdx.x * 4 + pair;     // batch element
    const bool is_neg = warp & 1;

    const int* __restrict__ tri = is_neg ? neg : pos;
    const int h = tri[elem * 3 + 0];
    const int r = tri[elem * 3 + 1];
    const int t = tri[elem * 3 + 2];

    const size_t lo = (size_t)lane;
    const float4* E  = (const float4*)ent;
    const float4* EP = (const float4*)entp;
    const float4* R  = (const float4*)rel;
    const float4* RP = (const float4*)relp;

    // all 6 gathers issued up front (MLP)
    float4 vh  = __ldg(E  + (size_t)h * 32 + lo);
    float4 vhp = __ldg(EP + (size_t)h * 32 + lo);
    float4 vt  = __ldg(E  + (size_t)t * 32 + lo);
    float4 vtp = __ldg(EP + (size_t)t * 32 + lo);
    float4 vr  = __ldg(R  + (size_t)r * 32 + lo);
    float4 vrp = __ldg(RP + (size_t)r * 32 + lo);

    // per-lane (headp.head - tailp.tail) partial, ONE butterfly
    float d0 = dot4(vhp, vh) - dot4(vtp, vt);
    #pragma unroll
    for (int o = 16; o > 0; o >>= 1)
        d0 += __shfl_xor_sync(0xFFFFFFFFu, d0, o);
    const float ds = d0;

    float dx = fmaf(vrp.x, ds, vh.x - vt.x + vr.x + EPS_V);
    float dy = fmaf(vrp.y, ds, vh.y - vt.y + vr.y + EPS_V);
    float dz = fmaf(vrp.z, ds, vh.z - vt.z + vr.z + EPS_V);
    float dw = fmaf(vrp.w, ds, vh.w - vt.w + vr.w + EPS_V);

    float ss = dx*dx + dy*dy + dz*dz + dw*dw;
    #pragma unroll
    for (int o = 16; o > 0; o >>= 1)
        ss += __shfl_xor_sync(0xFFFFFFFFu, ss, o);

    const float score = sqrtf(ss);

    __shared__ float scores[8];
    if (lane == 0) scores[warp] = score;
    __syncthreads();

    if (warp == 0) {
        float s = 0.0f;
        if (lane < 4) {
            float loss = scores[2 * lane] - scores[2 * lane + 1] + MARGIN;
            s = loss > 0.0f ? loss : 0.0f;
        }
        #pragma unroll
        for (int o = 2; o > 0; o >>= 1)
            s += __shfl_xor_sync(0xFFFFFFFFu, s, o);
        if (lane == 0)
            atomicAdd(out, s * (1.0f / (float)BATCH));
    }
}

extern "C" void kernel_launch(void* const* d_in, const int* in_sizes, int n_in,
                              void* d_out, int out_size)
{
    const float* ent   = (const float*)d_in[0];
    const float* entp  = (const float*)d_in[1];
    const float* rel   = (const float*)d_in[2];
    const float* relp  = (const float*)d_in[3];
    const int*   pos_x = (const int*)d_in[4];
    const int*   neg_x = (const int*)d_in[5];
    float*       out   = (float*)d_out;

    cudaMemsetAsync(out, 0, sizeof(float));

    const int blocks = BATCH / 4;  // 4 elements per block, 8 warps
    transd_kernel<<<blocks, 256>>>(ent, entp, rel, relp, pos_x, neg_x, out);
}

// round 15
// speedup vs baseline: 1.0059x; 1.0059x over previous
#include <cuda_runtime.h>
#include <math.h>

#define BATCH     262144
#define MARGIN    1.0f
#define EPS_V     1e-6f

__device__ __forceinline__ float dot4(float4 a, float4 b) {
    return fmaf(a.x, b.x, fmaf(a.y, b.y, fmaf(a.z, b.z, a.w * b.w)));
}

// CONVERGED OPTIMUM (R11 source, best measured 147.3us):
// - one warp per triple (6 x 512B coalesced row gathers, max MLP per reg budget)
// - 256-thread blocks, 8 blocks/SM -> 64 warps/SM (regs=30)
// - plain __ldg (cache-policy hints measured neutral-to-negative)
// - single block-level atomicAdd (measured free at 65536 blocks)
// - memset graph node for accumulator zero (measured free)
// Kernel runs at ~6.8 TB/s warm effective bandwidth on ~995MB compulsory
// random-gather traffic == the sm_103a random-512B-gather roofline.
__global__ __launch_bounds__(256, 8)
void transd_kernel(const float* __restrict__ ent,
                   const float* __restrict__ entp,
                   const float* __restrict__ rel,
                   const float* __restrict__ relp,
                   const int*   __restrict__ pos,
                   const int*   __restrict__ neg,
                   float*       __restrict__ out)
{
    const int lane = threadIdx.x & 31;
    const int warp = threadIdx.x >> 5;          // 0..7
    const int pair = warp >> 1;                 // 0..3
    const int elem = blockIdx.x * 4 + pair;     // batch element
    const bool is_neg = warp & 1;

    const int* __restrict__ tri = is_neg ? neg : pos;
    const int h = tri[elem * 3 + 0];
    const int r = tri[elem * 3 + 1];
    const int t = tri[elem * 3 + 2];

    const size_t lo = (size_t)lane;
    const float4* E  = (const float4*)ent;
    const float4* EP = (const float4*)entp;
    const float4* R  = (const float4*)rel;
    const float4* RP = (const float4*)relp;

    // all 6 gathers issued up front (MLP)
    float4 vh  = __ldg(E  + (size_t)h * 32 + lo);
    float4 vhp = __ldg(EP + (size_t)h * 32 + lo);
    float4 vt  = __ldg(E  + (size_t)t * 32 + lo);
    float4 vtp = __ldg(EP + (size_t)t * 32 + lo);
    float4 vr  = __ldg(R  + (size_t)r * 32 + lo);
    float4 vrp = __ldg(RP + (size_t)r * 32 + lo);

    // two dot partials, fused butterfly
    float sh = dot4(vhp, vh);
    float st = dot4(vtp, vt);
    #pragma unroll
    for (int o = 16; o > 0; o >>= 1) {
        sh += __shfl_xor_sync(0xFFFFFFFFu, sh, o);
        st += __shfl_xor_sync(0xFFFFFFFFu, st, o);
    }
    const float ds = sh - st;

    float dx = fmaf(vrp.x, ds, vh.x - vt.x + vr.x + EPS_V);
    float dy = fmaf(vrp.y, ds, vh.y - vt.y + vr.y + EPS_V);
    float dz = fmaf(vrp.z, ds, vh.z - vt.z + vr.z + EPS_V);
    float dw = fmaf(vrp.w, ds, vh.w - vt.w + vr.w + EPS_V);

    float ss = dx*dx + dy*dy + dz*dz + dw*dw;
    #pragma unroll
    for (int o = 16; o > 0; o >>= 1)
        ss += __shfl_xor_sync(0xFFFFFFFFu, ss, o);

    const float score = sqrtf(ss);

    __shared__ float scores[8];
    if (lane == 0) scores[warp] = score;
    __syncthreads();

    if (warp == 0) {
        float s = 0.0f;
        if (lane < 4) {
            float loss = scores[2 * lane] - scores[2 * lane + 1] + MARGIN;
            s = loss > 0.0f ? loss : 0.0f;
        }
        #pragma unroll
        for (int o = 2; o > 0; o >>= 1)
            s += __shfl_xor_sync(0xFFFFFFFFu, s, o);
        if (lane == 0)
            atomicAdd(out, s * (1.0f / (float)BATCH));
    }
}

extern "C" void kernel_launch(void* const* d_in, const int* in_sizes, int n_in,
                              void* d_out, int out_size)
{
    const float* ent   = (const float*)d_in[0];
    const float* entp  = (const float*)d_in[1];
    const float* rel   = (const float*)d_in[2];
    const float* relp  = (const float*)d_in[3];
    const int*   pos_x = (const int*)d_in[4];
    const int*   neg_x = (const int*)d_in[5];
    float*       out   = (float*)d_out;

    cudaMemsetAsync(out, 0, sizeof(float));

    const int blocks = BATCH / 4;  // 4 elements per block, 8 warps
    transd_kernel<<<blocks, 256>>>(ent, entp, rel, relp, pos_x, neg_x, out);
}

// round 16
// speedup vs baseline: 1.0328x; 1.0267x over previous
#include <cuda_runtime.h>
#include <math.h>

#define BATCH     262144
#define MARGIN    1.0f
#define EPS_V     1e-6f

__device__ __forceinline__ float dot4(float4 a, float4 b) {
    return fmaf(a.x, b.x, fmaf(a.y, b.y, fmaf(a.z, b.z, a.w * b.w)));
}

// FINAL — CONVERGED OPTIMUM (best measured 147.3us; draws 147-152):
// - one warp per triple: 6 x 512B perfectly-coalesced row gathers (float4/lane),
//   all issued back-to-back for max per-warp MLP within the register budget
// - 256-thread blocks, 8 blocks/SM -> 64 warps/SM resident (regs=30)
//   [A/B: 32 warps/SM slower; 512-thr blocks slower; 128-thr blocks 2.7x worse]
// - plain __ldg [A/B: evict_last hints neutral-to-negative; pinning -8%]
// - single block atomicAdd [A/B: two-stage reduce +4.5us; fence-accum +25us]
// - memset graph node zeroes out [A/B: node is free; in-kernel reset +25us]
// Runs at ~6.8 TB/s warm effective bandwidth on ~995MB compulsory random-
// gather traffic == the sm_103a random-512B-gather roofline (~85% of spec).
__global__ __launch_bounds__(256, 8)
void transd_kernel(const float* __restrict__ ent,
                   const float* __restrict__ entp,
                   const float* __restrict__ rel,
                   const float* __restrict__ relp,
                   const int*   __restrict__ pos,
                   const int*   __restrict__ neg,
                   float*       __restrict__ out)
{
    const int lane = threadIdx.x & 31;
    const int warp = threadIdx.x >> 5;          // 0..7
    const int pair = warp >> 1;                 // 0..3
    const int elem = blockIdx.x * 4 + pair;     // batch element
    const bool is_neg = warp & 1;

    const int* __restrict__ tri = is_neg ? neg : pos;
    const int h = tri[elem * 3 + 0];
    const int r = tri[elem * 3 + 1];
    const int t = tri[elem * 3 + 2];

    const size_t lo = (size_t)lane;
    const float4* E  = (const float4*)ent;
    const float4* EP = (const float4*)entp;
    const float4* R  = (const float4*)rel;
    const float4* RP = (const float4*)relp;

    // all 6 gathers issued up front (MLP)
    float4 vh  = __ldg(E  + (size_t)h * 32 + lo);
    float4 vhp = __ldg(EP + (size_t)h * 32 + lo);
    float4 vt  = __ldg(E  + (size_t)t * 32 + lo);
    float4 vtp = __ldg(EP + (size_t)t * 32 + lo);
    float4 vr  = __ldg(R  + (size_t)r * 32 + lo);
    float4 vrp = __ldg(RP + (size_t)r * 32 + lo);

    // two dot partials, fused butterfly
    float sh = dot4(vhp, vh);
    float st = dot4(vtp, vt);
    #pragma unroll
    for (int o = 16; o > 0; o >>= 1) {
        sh += __shfl_xor_sync(0xFFFFFFFFu, sh, o);
        st += __shfl_xor_sync(0xFFFFFFFFu, st, o);
    }
    const float ds = sh - st;

    float dx = fmaf(vrp.x, ds, vh.x - vt.x + vr.x + EPS_V);
    float dy = fmaf(vrp.y, ds, vh.y - vt.y + vr.y + EPS_V);
    float dz = fmaf(vrp.z, ds, vh.z - vt.z + vr.z + EPS_V);
    float dw = fmaf(vrp.w, ds, vh.w - vt.w + vr.w + EPS_V);

    float ss = dx*dx + dy*dy + dz*dz + dw*dw;
    #pragma unroll
    for (int o = 16; o > 0; o >>= 1)
        ss += __shfl_xor_sync(0xFFFFFFFFu, ss, o);

    const float score = sqrtf(ss);

    __shared__ float scores[8];
    if (lane == 0) scores[warp] = score;
    __syncthreads();

    if (warp == 0) {
        float s = 0.0f;
        if (lane < 4) {
            float loss = scores[2 * lane] - scores[2 * lane + 1] + MARGIN;
            s = loss > 0.0f ? loss : 0.0f;
        }
        #pragma unroll
        for (int o = 2; o > 0; o >>= 1)
            s += __shfl_xor_sync(0xFFFFFFFFu, s, o);
        if (lane == 0)
            atomicAdd(out, s * (1.0f / (float)BATCH));
    }
}

extern "C" void kernel_launch(void* const* d_in, const int* in_sizes, int n_in,
                              void* d_out, int out_size)
{
    const float* ent   = (const float*)d_in[0];
    const float* entp  = (const float*)d_in[1];
    const float* rel   = (const float*)d_in[2];
    const float* relp  = (const float*)d_in[3];
    const int*   pos_x = (const int*)d_in[4];
    const int*   neg_x = (const int*)d_in[5];
    float*       out   = (float*)d_out;

    cudaMemsetAsync(out, 0, sizeof(float));

    const int blocks = BATCH / 4;  // 4 elements per block, 8 warps
    transd_kernel<<<blocks, 256>>>(ent, entp, rel, relp, pos_x, neg_x, out);
}